// round 9
// baseline (speedup 1.0000x reference)
#include <cuda_runtime.h>

#define FULLMASK 0xffffffffu

static constexpr int B_V   = 8192;
static constexpr int KN    = 64;
static constexpr int TASKS = 2 * B_V;   // 16384 (vertex, side) tasks
static constexpr int IN2   = 132;
static constexpr int HID   = 84;

// Scratch (no cudaMalloc allowed)
__device__ float g_mean[TASKS * IN2];   // 8.6 MB

// ---------------------------------------------------------------------------
// dummy kernel: shifts ncu's -s 5 capture onto k_mean (4 launches per call)
// ---------------------------------------------------------------------------
__global__ void k_dummy() {}

// ---------------------------------------------------------------------------
// Kernel 1: masked mean. 8 warps/CTA, 2 warps per task (each owns 32 neighbors).
// Tables via LDG (L1-hot). Lane mapping:
//   0-4  : dense dims [4c,4c+4)
//   5-8  : t0 chunks
//   9    : t6 tail (row floats 12..15 -> out dims 128..131)  [same line as 29-31]
//   10-12: dup dense (t1 handled by ballot)
//   13-28: t2,t3,t4,t5 chunks
//   29-31: t6 floats 0..11
// t1 (4 rows) via ballot-histogram; lanes 9-12 write its 4 chunks.
// ---------------------------------------------------------------------------
static constexpr int MEAN_TPC  = 4;                    // tasks per CTA
static constexpr int MEAN_CTAS = TASKS / MEAN_TPC;     // 4096

__global__ void __launch_bounds__(256) k_mean(
    const float* __restrict__ device_dense,
    const int*   __restrict__ device_cat,
    const float* __restrict__ t0, const float* __restrict__ t1,
    const float* __restrict__ t2, const float* __restrict__ t3,
    const float* __restrict__ t4, const float* __restrict__ t5,
    const float* __restrict__ t6,
    const int* __restrict__ bot_neibrs, const int* __restrict__ normal_neibrs,
    const int* __restrict__ bot_counts, const int* __restrict__ normal_counts)
{
    __shared__ int    sCat[8][32 * 8];        // per-warp cat ids, 8 KB
    __shared__ float4 sPart[MEAN_TPC][33];    // odd-warp partials
    __shared__ float4 sT1[MEAN_TPC];          // odd-warp lane9 accT1

    int tid  = threadIdx.x;
    int w    = tid >> 5;          // 0..7
    int lane = tid & 31;
    int tl   = w >> 1;            // local task 0..3
    int half = w & 1;             // which 32-neighbor half

    int task = blockIdx.x * MEAN_TPC + tl;
    int b    = task >> 1;
    int side = task & 1;

    const int* neib = side ? normal_neibrs : bot_neibrs;
    int cnt = side ? normal_counts[b] : bot_counts[b];
    cnt = min(max(cnt, 1), KN);

    int myN = min(cnt - half * 32, 32);
    if (myN < 0) myN = 0;

    // own neighbor ids, one per lane
    int i0 = neib[b * KN + half * 32 + lane];

    // ---- prefetch cat ids (shfl unconditional, clamped; store predicated) ----
    int tot = myN * 7;
    for (int r = 0; r * 32 < tot; ++r) {
        int flat = r * 32 + lane;
        int n  = flat / 7;
        int tt = flat - n * 7;
        int nclamp = min(n, 31);
        int idx = __shfl_sync(FULLMASK, i0, nclamp);
        if (flat < tot)
            sCat[w][n * 8 + tt] = __ldg(device_cat + (size_t)idx * 7 + tt);
    }
    __syncwarp();

    // ---- per-lane chunk mapping ----
    int  c    = lane;
    int  m    = (c < 5) ? 0 : (c - 5);
    int  t    = m >> 2;
    int  e4   = (m & 3) * 4;
    bool isT6Tail = (lane == 9);
    bool isT1Dup  = (lane >= 10 && lane <= 12);
    bool isBallot = (lane >= 9 && lane <= 12);      // t1 chunk owners
    bool isDense  = (c < 5) || isT1Dup;
    const float* base;
    switch (t) {
        case 0: base = t0; break; case 1: base = t1; break;
        case 2: base = t2; break; case 3: base = t3; break;
        case 4: base = t4; break; case 5: base = t5; break;
        default: base = t6; break;
    }
    int denseSub = (c < 5) ? 4 * c : 0;

    // ---- main accumulation over own range ----
    float4 acc = make_float4(0.f, 0.f, 0.f, 0.f);
    #pragma unroll 8
    for (int n = 0; n < myN; ++n) {
        int idx = __shfl_sync(FULLMASK, i0, n);
        int catT = sCat[w][n * 8 + t];            // per-lane table cat
        int cat6 = sCat[w][n * 8 + 6];
        const float4* p;
        if (isT6Tail)
            p = reinterpret_cast<const float4*>(t6 + (size_t)cat6 * 16 + 12); // same line as lanes 29-31
        else if (isDense)
            p = reinterpret_cast<const float4*>(device_dense + (size_t)idx * 20 + denseSub);
        else
            p = reinterpret_cast<const float4*>(base + (size_t)catT * 16 + e4);
        float4 v = __ldg(p);
        acc.x += v.x; acc.y += v.y; acc.z += v.z; acc.w += v.w;
    }

    // ---- t1 contribution via ballot histogram (4 possible rows) ----
    float4 accT1 = make_float4(0.f, 0.f, 0.f, 0.f);
    {
        int c1 = sCat[w][lane * 8 + 1];           // lane n -> neighbor n's cat1
        #pragma unroll
        for (int v = 0; v < 4; ++v) {
            unsigned mk = __ballot_sync(FULLMASK, (lane < myN) && (c1 == v));
            float cv = (float)__popc(mk);
            if (isBallot) {
                float4 row = __ldg(reinterpret_cast<const float4*>(t1 + v * 16 + e4));
                accT1.x += cv * row.x; accT1.y += cv * row.y;
                accT1.z += cv * row.z; accT1.w += cv * row.w;
            }
        }
        if (isT1Dup) acc = accT1;                 // lanes 10-12: replace dup-dense junk
        // lane 9 keeps acc (t6 tail) AND accT1 separately
    }

    // ---- combine partner halves ----
    if (half == 1) {
        sPart[tl][lane] = acc;
        if (lane == 9) sT1[tl] = accT1;
    }
    __syncthreads();
    if (half == 0) {
        float4 p = sPart[tl][lane];
        acc.x += p.x; acc.y += p.y; acc.z += p.z; acc.w += p.w;
        float inv = 1.0f / (float)cnt;
        float4 o4 = make_float4(acc.x * inv, acc.y * inv, acc.z * inv, acc.w * inv);
        // output offset: dense 4c; lane 9 -> 128; others 20+4m
        int outOff = (c < 5) ? 4 * c : (isT6Tail ? 128 : 20 + 4 * m);
        *reinterpret_cast<float4*>(g_mean + (size_t)task * IN2 + outOff) = o4;
        if (lane == 9) {
            float4 pt = sT1[tl];
            float4 o1 = make_float4((accT1.x + pt.x) * inv, (accT1.y + pt.y) * inv,
                                    (accT1.z + pt.z) * inv, (accT1.w + pt.w) * inv);
            *reinterpret_cast<float4*>(g_mean + (size_t)task * IN2 + 36) = o1; // t1 chunk m=4
        }
    }
}

// ---------------------------------------------------------------------------
// packed f32x2 helpers (sm_100+)
// ---------------------------------------------------------------------------
__device__ __forceinline__ unsigned long long pk2(float lo, float hi) {
    unsigned long long r;
    asm("mov.b64 %0, {%1, %2};" : "=l"(r) : "f"(lo), "f"(hi));
    return r;
}
__device__ __forceinline__ void fma2(unsigned long long& d,
                                     unsigned long long a, unsigned long long b) {
    asm("fma.rn.f32x2 %0, %1, %2, %0;" : "+l"(d) : "l"(a), "l"(b));
}
__device__ __forceinline__ float2 upk2(unsigned long long v) {
    float2 f;
    asm("mov.b64 {%0, %1}, %2;" : "=f"(f.x), "=f"(f.y) : "l"(v));
    return f;
}

// ---------------------------------------------------------------------------
// Kernel 2: fused MLP chain (R4 best variant: weights in smem).
// 256 CTAs x 256 thr; CTA = 64 tasks (32 vertices).
// ---------------------------------------------------------------------------
static constexpr int BM = 64;

static constexpr int O_WAGG  = 0;                       // [132][64]
static constexpr int O_WATT  = O_WAGG  + 132 * 64;      // [96][84]
static constexpr int O_WSELF = O_WATT  + 96 * 84;       // [32][64]
static constexpr int O_W2    = O_WSELF + 32 * 64;       // [84] pad 96
static constexpr int O_BAGG  = O_W2    + 96;
static constexpr int O_BATT  = O_BAGG  + 64;            // [84] pad 96
static constexpr int O_BSELF = O_BATT  + 96;
static constexpr int O_B2    = O_BSELF + 64;            // pad 16
static constexpr int O_SCORE = O_B2    + 16;            // [64]
static constexpr int O_OVER  = O_SCORE + 64;            // overlay sA[132][68]/sHT[96][68]
static constexpr int SA_LD   = 68;
static constexpr int SMEM_FLOATS = O_OVER + 132 * SA_LD;
static constexpr int FUSED_SMEM  = SMEM_FLOATS * 4;     // ~111.7 KB

__global__ void __launch_bounds__(256) k_fused(
    const float* __restrict__ W_agg,  const float* __restrict__ b_agg,
    const float* __restrict__ W_attn, const float* __restrict__ b_attn,
    const float* __restrict__ W_attn2,const float* __restrict__ b_attn2,
    const float* __restrict__ W_self, const float* __restrict__ b_self,
    const float* __restrict__ channel_dense,
    const float* __restrict__ channel_id_emb,
    const int*   __restrict__ channel_ids,
    const int*   __restrict__ vertices,
    float* __restrict__ out)
{
    extern __shared__ float sm[];
    int tid  = threadIdx.x;
    int warp = tid >> 5;
    int lane = tid & 31;
    int tbase = blockIdx.x * BM;
    int vbase = blockIdx.x * (BM / 2);

    // ---- weights ----
    for (int e = tid; e < (132 * 64) / 4; e += 256)
        reinterpret_cast<float4*>(sm + O_WAGG)[e] = reinterpret_cast<const float4*>(W_agg)[e];
    for (int e = tid; e < (96 * 84) / 4; e += 256)
        reinterpret_cast<float4*>(sm + O_WATT)[e] = reinterpret_cast<const float4*>(W_attn)[e];
    for (int e = tid; e < (32 * 64) / 4; e += 256)
        reinterpret_cast<float4*>(sm + O_WSELF)[e] = reinterpret_cast<const float4*>(W_self)[e];
    if (tid < 84) sm[O_W2 + tid]   = W_attn2[tid];
    if (tid < 64) sm[O_BAGG + tid] = b_agg[tid];
    if (tid >= 64 && tid < 148)  sm[O_BATT + tid - 64]   = b_attn[tid - 64];
    if (tid >= 148 && tid < 212) sm[O_BSELF + tid - 148] = b_self[tid - 148];
    if (tid == 212) sm[O_B2] = b_attn2[0];

    // ---- stage A (transposed): sA[k][row], 64 rows ----
    float* sA = sm + O_OVER;
    for (int e = tid; e < BM * 33; e += 256) {
        int row = e / 33, cch = e - row * 33;
        float4 v = *reinterpret_cast<const float4*>(g_mean + (size_t)(tbase + row) * IN2 + cch * 4);
        sA[(4 * cch + 0) * SA_LD + row] = v.x;
        sA[(4 * cch + 1) * SA_LD + row] = v.y;
        sA[(4 * cch + 2) * SA_LD + row] = v.z;
        sA[(4 * cch + 3) * SA_LD + row] = v.w;
    }
    __syncthreads();

    // ---- phase 1: h = sA^T @ W_agg ; warp -> 8 rows (4 pairs), lane -> 2 cols
    unsigned long long acc1[4][2];
    #pragma unroll
    for (int p = 0; p < 4; ++p) { acc1[p][0] = 0ull; acc1[p][1] = 0ull; }
    {
        const float* wa = sm + O_WAGG;
        #pragma unroll 4
        for (int k = 0; k < IN2; ++k) {
            ulonglong2 aA = *reinterpret_cast<const ulonglong2*>(&sA[k * SA_LD + warp * 8]);
            ulonglong2 aB = *reinterpret_cast<const ulonglong2*>(&sA[k * SA_LD + warp * 8 + 4]);
            unsigned long long b0d = pk2(wa[k * 64 + lane],      wa[k * 64 + lane]);
            unsigned long long b1d = pk2(wa[k * 64 + lane + 32], wa[k * 64 + lane + 32]);
            fma2(acc1[0][0], aA.x, b0d); fma2(acc1[0][1], aA.x, b1d);
            fma2(acc1[1][0], aA.y, b0d); fma2(acc1[1][1], aA.y, b1d);
            fma2(acc1[2][0], aB.x, b0d); fma2(acc1[2][1], aB.x, b1d);
            fma2(acc1[3][0], aB.y, b0d); fma2(acc1[3][1], aB.y, b1d);
        }
    }
    __syncthreads();   // overlay becomes sHT

    // ---- write h(+bias) transposed; fill chv rows 64..95 ----
    float* sHT = sm + O_OVER;   // [96][SA_LD]
    {
        float ba0 = sm[O_BAGG + lane], ba1 = sm[O_BAGG + lane + 32];
        #pragma unroll
        for (int p = 0; p < 4; ++p) {
            int row = warp * 8 + 2 * p;
            float2 v0 = upk2(acc1[p][0]);
            float2 v1 = upk2(acc1[p][1]);
            sHT[lane * SA_LD + row]            = v0.x + ba0;
            sHT[lane * SA_LD + row + 1]        = v0.y + ba0;
            sHT[(lane + 32) * SA_LD + row]     = v1.x + ba1;
            sHT[(lane + 32) * SA_LD + row + 1] = v1.y + ba1;
        }
    }
    for (int e = tid; e < (BM / 2) * 32; e += 256) {
        int i = e >> 5, j = e & 31;
        int v = vertices[vbase + i];
        float val = (j < 16) ? channel_dense[(size_t)v * 16 + j]
                             : channel_id_emb[(size_t)channel_ids[v] * 16 + (j - 16)];
        sHT[(64 + j) * SA_LD + 2 * i]     = val;
        sHT[(64 + j) * SA_LD + 2 * i + 1] = val;
    }
    __syncthreads();

    // ---- phase 2: hid = relu(z @ W_attn + b); score = hid . W_attn2 ----
    unsigned long long acc2[4][3];
    #pragma unroll
    for (int p = 0; p < 4; ++p) { acc2[p][0] = 0ull; acc2[p][1] = 0ull; acc2[p][2] = 0ull; }
    {
        const float* wt = sm + O_WATT;
        bool has3 = (lane < HID - 64);
        #pragma unroll 4
        for (int k = 0; k < 96; ++k) {
            ulonglong2 aA = *reinterpret_cast<const ulonglong2*>(&sHT[k * SA_LD + warp * 8]);
            ulonglong2 aB = *reinterpret_cast<const ulonglong2*>(&sHT[k * SA_LD + warp * 8 + 4]);
            float w0 = wt[k * HID + lane];
            float w1 = wt[k * HID + lane + 32];
            float w2v = has3 ? wt[k * HID + lane + 64] : 0.f;
            unsigned long long w0d = pk2(w0, w0);
            unsigned long long w1d = pk2(w1, w1);
            unsigned long long w2d = pk2(w2v, w2v);
            fma2(acc2[0][0], aA.x, w0d); fma2(acc2[0][1], aA.x, w1d); fma2(acc2[0][2], aA.x, w2d);
            fma2(acc2[1][0], aA.y, w0d); fma2(acc2[1][1], aA.y, w1d); fma2(acc2[1][2], aA.y, w2d);
            fma2(acc2[2][0], aB.x, w0d); fma2(acc2[2][1], aB.x, w1d); fma2(acc2[2][2], aB.x, w2d);
            fma2(acc2[3][0], aB.y, w0d); fma2(acc2[3][1], aB.y, w1d); fma2(acc2[3][2], aB.y, w2d);
        }
    }
    {
        float bt0 = sm[O_BATT + lane], bt1 = sm[O_BATT + lane + 32];
        float bt2 = (lane < HID - 64) ? sm[O_BATT + lane + 64] : 0.f;
        float wv0 = sm[O_W2 + lane],  wv1 = sm[O_W2 + lane + 32];
        float wv2 = (lane < HID - 64) ? sm[O_W2 + lane + 64] : 0.f;
        float p8[8];
        #pragma unroll
        for (int p = 0; p < 4; ++p) {
            float2 c0 = upk2(acc2[p][0]);
            float2 c1 = upk2(acc2[p][1]);
            float2 c2 = upk2(acc2[p][2]);
            p8[2 * p]     = fmaxf(c0.x + bt0, 0.f) * wv0 + fmaxf(c1.x + bt1, 0.f) * wv1
                          + fmaxf(c2.x + bt2, 0.f) * wv2;
            p8[2 * p + 1] = fmaxf(c0.y + bt0, 0.f) * wv0 + fmaxf(c1.y + bt1, 0.f) * wv1
                          + fmaxf(c2.y + bt2, 0.f) * wv2;
        }
        #pragma unroll
        for (int o = 16; o; o >>= 1) {
            #pragma unroll
            for (int r = 0; r < 8; ++r) p8[r] += __shfl_xor_sync(FULLMASK, p8[r], o);
        }
        if (lane == 0) {
            #pragma unroll
            for (int r = 0; r < 8; ++r) sm[O_SCORE + warp * 8 + r] = p8[r];
        }
    }
    __syncthreads();

    // ---- phase 3: per vertex finalize; warp owns vertices warp*4..+4 ----
    #pragma unroll
    for (int s = 0; s < 4; ++s) {
        int vl = warp * 4 + s;
        int vg = vbase + vl;
        float s0 = sm[O_SCORE + 2 * vl];
        float s1 = sm[O_SCORE + 2 * vl + 1];
        float mx = fmaxf(s0, s1);
        float e0 = __expf(s0 - mx), e1 = __expf(s1 - mx);
        float a0 = e0 / (e0 + e1), a1 = 1.f - a0;

        int r0i = 2 * vl, r1i = 2 * vl + 1;
        float g0 = a0 * sHT[lane * SA_LD + r0i]        + a1 * sHT[lane * SA_LD + r1i];
        float g1 = a0 * sHT[(lane + 32) * SA_LD + r0i] + a1 * sHT[(lane + 32) * SA_LD + r1i];
        out[(size_t)vg * 128 + lane]      = fmaxf(g0, 0.f);
        out[(size_t)vg * 128 + lane + 32] = fmaxf(g1, 0.f);

        float r0 = sm[O_BSELF + lane], r1 = sm[O_BSELF + lane + 32];
        const float* ws = sm + O_WSELF;
        #pragma unroll
        for (int d = 0; d < 32; ++d) {
            float xv = sHT[(64 + d) * SA_LD + r0i];
            r0 += xv * ws[d * 64 + lane];
            r1 += xv * ws[d * 64 + lane + 32];
        }
        out[(size_t)vg * 128 + 64 + lane] = fmaxf(r0, 0.f);
        out[(size_t)vg * 128 + 96 + lane] = fmaxf(r1, 0.f);
    }
}

// ---------------------------------------------------------------------------
extern "C" void kernel_launch(void* const* d_in, const int* in_sizes, int n_in,
                              void* d_out, int out_size)
{
    const float* channel_dense  = (const float*)d_in[0];
    const float* device_dense   = (const float*)d_in[1];
    const float* channel_id_emb = (const float*)d_in[2];
    const float* t0 = (const float*)d_in[3];
    const float* t1 = (const float*)d_in[4];
    const float* t2 = (const float*)d_in[5];
    const float* t3 = (const float*)d_in[6];
    const float* t4 = (const float*)d_in[7];
    const float* t5 = (const float*)d_in[8];
    const float* t6 = (const float*)d_in[9];
    const float* W_agg   = (const float*)d_in[10];
    const float* b_agg   = (const float*)d_in[11];
    const float* W_self  = (const float*)d_in[12];
    const float* b_self  = (const float*)d_in[13];
    const float* W_attn  = (const float*)d_in[14];
    const float* b_attn  = (const float*)d_in[15];
    const float* W_attn2 = (const float*)d_in[16];
    const float* b_attn2 = (const float*)d_in[17];
    const int* channel_ids   = (const int*)d_in[18];
    const int* device_cat    = (const int*)d_in[19];
    const int* vertices      = (const int*)d_in[20];
    const int* bot_neibrs    = (const int*)d_in[21];
    const int* normal_neibrs = (const int*)d_in[22];
    const int* bot_counts    = (const int*)d_in[23];
    const int* normal_counts = (const int*)d_in[24];
    float* out = (float*)d_out;

    static bool attr_set = false;
    if (!attr_set) {
        cudaFuncSetAttribute(k_fused, cudaFuncAttributeMaxDynamicSharedMemorySize, FUSED_SMEM);
        attr_set = true;
    }

    // 4 launches per call so ncu's "-s 5" lands on k_mean (5 mod 4 == 1)
    k_dummy<<<1, 32>>>();

    k_mean<<<MEAN_CTAS, 256>>>(device_dense, device_cat,
                               t0, t1, t2, t3, t4, t5, t6,
                               bot_neibrs, normal_neibrs,
                               bot_counts, normal_counts);

    k_fused<<<TASKS / BM, 256, FUSED_SMEM>>>(
        W_agg, b_agg, W_attn, b_attn, W_attn2, b_attn2, W_self, b_self,
        channel_dense, channel_id_emb, channel_ids, vertices, out);

    k_dummy<<<1, 32>>>();
}

// round 10
// speedup vs baseline: 1.1813x; 1.1813x over previous
#include <cuda_runtime.h>

#define FULLMASK 0xffffffffu

static constexpr int B_V   = 8192;
static constexpr int KN    = 64;
static constexpr int TASKS = 2 * B_V;   // 16384 (vertex, side) tasks
static constexpr int IN2   = 132;
static constexpr int HID   = 84;

// Scratch (no cudaMalloc allowed)
__device__ float g_mean[TASKS * IN2];   // 8.6 MB

// ---------------------------------------------------------------------------
// Kernel 1: masked mean (R8-proven). 8 warps/CTA, 2 warps per task.
// Tables via LDG (L1-hot). Lane c<5: dense dims; lanes 5..31: emb dims.
// t1 (4 rows) via ballot-histogram. Tail dims [128,132) strided post-pass.
// ---------------------------------------------------------------------------
static constexpr int MEAN_TPC  = 4;                    // tasks per CTA
static constexpr int MEAN_CTAS = TASKS / MEAN_TPC;     // 4096

__global__ void __launch_bounds__(256) k_mean(
    const float* __restrict__ device_dense,
    const int*   __restrict__ device_cat,
    const float* __restrict__ t0, const float* __restrict__ t1,
    const float* __restrict__ t2, const float* __restrict__ t3,
    const float* __restrict__ t4, const float* __restrict__ t5,
    const float* __restrict__ t6,
    const int* __restrict__ bot_neibrs, const int* __restrict__ normal_neibrs,
    const int* __restrict__ bot_counts, const int* __restrict__ normal_counts)
{
    __shared__ int    sCat[8][32 * 8];        // per-warp cat ids, 8 KB
    __shared__ float4 sPart[MEAN_TPC][33];    // odd-warp partials
    __shared__ float4 sTail[MEAN_TPC];

    int tid  = threadIdx.x;
    int w    = tid >> 5;          // 0..7
    int lane = tid & 31;
    int tl   = w >> 1;            // local task 0..3
    int half = w & 1;             // which 32-neighbor half

    int task = blockIdx.x * MEAN_TPC + tl;
    int b    = task >> 1;
    int side = task & 1;

    const int* neib = side ? normal_neibrs : bot_neibrs;
    int cnt = side ? normal_counts[b] : bot_counts[b];
    cnt = min(max(cnt, 1), KN);

    int myN = min(cnt - half * 32, 32);
    if (myN < 0) myN = 0;

    // own neighbor ids, one per lane
    int i0 = neib[b * KN + half * 32 + lane];

    // ---- prefetch cat ids (shfl unconditional, clamped; store predicated) ----
    int tot = myN * 7;
    for (int r = 0; r * 32 < tot; ++r) {
        int flat = r * 32 + lane;
        int n  = flat / 7;
        int tt = flat - n * 7;
        int nclamp = min(n, 31);
        int idx = __shfl_sync(FULLMASK, i0, nclamp);
        if (flat < tot)
            sCat[w][n * 8 + tt] = __ldg(device_cat + (size_t)idx * 7 + tt);
    }
    __syncwarp();

    // ---- per-lane chunk mapping ----
    // lanes 0-4: dense; 5-8:t0, 9-12:t1(ballot path), 13-16:t2,
    // 17-20:t3, 21-24:t4, 25-28:t5, 29-31:t6[0..11]
    int  c       = lane;
    int  m       = (c < 5) ? 0 : (c - 5);
    int  t       = m >> 2;
    int  e4      = (m & 3) * 4;
    bool isT1    = (t == 1) && (c >= 5);
    bool isDense = (c < 5) || isT1;        // t1 lanes ride the dense dup address
    const float* base;
    switch (t) {
        case 0: base = t0; break; case 1: base = t1; break;
        case 2: base = t2; break; case 3: base = t3; break;
        case 4: base = t4; break; case 5: base = t5; break;
        default: base = t6; break;
    }
    int denseSub = (c < 5) ? 4 * c : 0;    // t1 lanes dup lane 0's chunk

    // ---- main accumulation over own range ----
    float4 acc = make_float4(0.f, 0.f, 0.f, 0.f);
    #pragma unroll 8
    for (int n = 0; n < myN; ++n) {
        int idx = __shfl_sync(FULLMASK, i0, n);
        int cat = sCat[w][n * 8 + t];             // broadcast LDS
        const float4* p = isDense
            ? reinterpret_cast<const float4*>(device_dense + (size_t)idx * 20 + denseSub)
            : reinterpret_cast<const float4*>(base + (size_t)cat * 16 + e4);
        float4 v = __ldg(p);
        acc.x += v.x; acc.y += v.y; acc.z += v.z; acc.w += v.w;
    }

    // ---- t1 contribution via ballot histogram (4 possible rows) ----
    {
        int c1 = sCat[w][lane * 8 + 1];           // lane n -> neighbor n's cat1
        float4 accT1 = make_float4(0.f, 0.f, 0.f, 0.f);
        #pragma unroll
        for (int v = 0; v < 4; ++v) {
            unsigned mk = __ballot_sync(FULLMASK, (lane < myN) && (c1 == v));
            float cv = (float)__popc(mk);
            if (isT1) {
                float4 row = __ldg(reinterpret_cast<const float4*>(t1 + v * 16 + e4));
                accT1.x += cv * row.x; accT1.y += cv * row.y;
                accT1.z += cv * row.z; accT1.w += cv * row.w;
            }
        }
        if (isT1) acc = accT1;
    }

    // ---- tail chunk (dims 128..131 = t6 row floats 12..15), strided ----
    float4 acc2 = make_float4(0.f, 0.f, 0.f, 0.f);
    for (int n = lane; n < myN; n += 32) {
        int c6 = sCat[w][n * 8 + 6];
        float4 v = __ldg(reinterpret_cast<const float4*>(t6 + (size_t)c6 * 16 + 12));
        acc2.x += v.x; acc2.y += v.y; acc2.z += v.z; acc2.w += v.w;
    }
    #pragma unroll
    for (int o = 16; o; o >>= 1) {
        acc2.x += __shfl_xor_sync(FULLMASK, acc2.x, o);
        acc2.y += __shfl_xor_sync(FULLMASK, acc2.y, o);
        acc2.z += __shfl_xor_sync(FULLMASK, acc2.z, o);
        acc2.w += __shfl_xor_sync(FULLMASK, acc2.w, o);
    }

    // ---- combine partner halves ----
    if (half == 1) {
        sPart[tl][lane] = acc;
        if (lane == 0) sTail[tl] = acc2;
    }
    __syncthreads();
    if (half == 0) {
        float4 p = sPart[tl][lane];
        acc.x += p.x; acc.y += p.y; acc.z += p.z; acc.w += p.w;
        float inv = 1.0f / (float)cnt;
        float4 o4 = make_float4(acc.x * inv, acc.y * inv, acc.z * inv, acc.w * inv);
        int outOff = (c < 5) ? 4 * c : 20 + 4 * m;
        *reinterpret_cast<float4*>(g_mean + (size_t)task * IN2 + outOff) = o4;
        if (lane == 0) {
            float4 pt = sTail[tl];
            float4 o2 = make_float4((acc2.x + pt.x) * inv, (acc2.y + pt.y) * inv,
                                    (acc2.z + pt.z) * inv, (acc2.w + pt.w) * inv);
            *reinterpret_cast<float4*>(g_mean + (size_t)task * IN2 + 128) = o2;
        }
    }
}

// ---------------------------------------------------------------------------
// packed f32x2 helpers (sm_100+)
// ---------------------------------------------------------------------------
__device__ __forceinline__ unsigned long long pk2(float lo, float hi) {
    unsigned long long r;
    asm("mov.b64 %0, {%1, %2};" : "=l"(r) : "f"(lo), "f"(hi));
    return r;
}
__device__ __forceinline__ void fma2(unsigned long long& d,
                                     unsigned long long a, unsigned long long b) {
    asm("fma.rn.f32x2 %0, %1, %2, %0;" : "+l"(d) : "l"(a), "l"(b));
}
__device__ __forceinline__ float2 upk2(unsigned long long v) {
    float2 f;
    asm("mov.b64 {%0, %1}, %2;" : "=f"(f.x), "=f"(f.y) : "l"(v));
    return f;
}

// ---------------------------------------------------------------------------
// Kernel 2: fused MLP chain (R4 structure, weights in smem) + explicit
// 2-CTA/SM residency request: 2 x 111.7KB = 223.4KB <= 227KB smem/SM,
// launch_bounds(256,2) caps regs at 128 (128*512 = 64K RF exactly).
// ---------------------------------------------------------------------------
static constexpr int BM = 64;

static constexpr int O_WAGG  = 0;                       // [132][64]
static constexpr int O_WATT  = O_WAGG  + 132 * 64;      // [96][84]
static constexpr int O_WSELF = O_WATT  + 96 * 84;       // [32][64]
static constexpr int O_W2    = O_WSELF + 32 * 64;       // [84] pad 96
static constexpr int O_BAGG  = O_W2    + 96;
static constexpr int O_BATT  = O_BAGG  + 64;            // [84] pad 96
static constexpr int O_BSELF = O_BATT  + 96;
static constexpr int O_B2    = O_BSELF + 64;            // pad 16
static constexpr int O_SCORE = O_B2    + 16;            // [64]
static constexpr int O_OVER  = O_SCORE + 64;            // overlay sA[132][68]/sHT[96][68]
static constexpr int SA_LD   = 68;
static constexpr int SMEM_FLOATS = O_OVER + 132 * SA_LD;
static constexpr int FUSED_SMEM  = SMEM_FLOATS * 4;     // ~111.7 KB

__global__ void __launch_bounds__(256, 2) k_fused(
    const float* __restrict__ W_agg,  const float* __restrict__ b_agg,
    const float* __restrict__ W_attn, const float* __restrict__ b_attn,
    const float* __restrict__ W_attn2,const float* __restrict__ b_attn2,
    const float* __restrict__ W_self, const float* __restrict__ b_self,
    const float* __restrict__ channel_dense,
    const float* __restrict__ channel_id_emb,
    const int*   __restrict__ channel_ids,
    const int*   __restrict__ vertices,
    float* __restrict__ out)
{
    extern __shared__ float sm[];
    int tid  = threadIdx.x;
    int warp = tid >> 5;
    int lane = tid & 31;
    int tbase = blockIdx.x * BM;
    int vbase = blockIdx.x * (BM / 2);

    // ---- weights ----
    for (int e = tid; e < (132 * 64) / 4; e += 256)
        reinterpret_cast<float4*>(sm + O_WAGG)[e] = reinterpret_cast<const float4*>(W_agg)[e];
    for (int e = tid; e < (96 * 84) / 4; e += 256)
        reinterpret_cast<float4*>(sm + O_WATT)[e] = reinterpret_cast<const float4*>(W_attn)[e];
    for (int e = tid; e < (32 * 64) / 4; e += 256)
        reinterpret_cast<float4*>(sm + O_WSELF)[e] = reinterpret_cast<const float4*>(W_self)[e];
    if (tid < 84) sm[O_W2 + tid]   = W_attn2[tid];
    if (tid < 64) sm[O_BAGG + tid] = b_agg[tid];
    if (tid >= 64 && tid < 148)  sm[O_BATT + tid - 64]   = b_attn[tid - 64];
    if (tid >= 148 && tid < 212) sm[O_BSELF + tid - 148] = b_self[tid - 148];
    if (tid == 212) sm[O_B2] = b_attn2[0];

    // ---- stage A (transposed): sA[k][row], 64 rows ----
    float* sA = sm + O_OVER;
    for (int e = tid; e < BM * 33; e += 256) {
        int row = e / 33, cch = e - row * 33;
        float4 v = *reinterpret_cast<const float4*>(g_mean + (size_t)(tbase + row) * IN2 + cch * 4);
        sA[(4 * cch + 0) * SA_LD + row] = v.x;
        sA[(4 * cch + 1) * SA_LD + row] = v.y;
        sA[(4 * cch + 2) * SA_LD + row] = v.z;
        sA[(4 * cch + 3) * SA_LD + row] = v.w;
    }
    __syncthreads();

    // ---- phase 1: h = sA^T @ W_agg ; warp -> 8 rows (4 pairs), lane -> 2 cols
    unsigned long long acc1[4][2];
    #pragma unroll
    for (int p = 0; p < 4; ++p) { acc1[p][0] = 0ull; acc1[p][1] = 0ull; }
    {
        const float* wa = sm + O_WAGG;
        #pragma unroll 4
        for (int k = 0; k < IN2; ++k) {
            ulonglong2 aA = *reinterpret_cast<const ulonglong2*>(&sA[k * SA_LD + warp * 8]);
            ulonglong2 aB = *reinterpret_cast<const ulonglong2*>(&sA[k * SA_LD + warp * 8 + 4]);
            unsigned long long b0d = pk2(wa[k * 64 + lane],      wa[k * 64 + lane]);
            unsigned long long b1d = pk2(wa[k * 64 + lane + 32], wa[k * 64 + lane + 32]);
            fma2(acc1[0][0], aA.x, b0d); fma2(acc1[0][1], aA.x, b1d);
            fma2(acc1[1][0], aA.y, b0d); fma2(acc1[1][1], aA.y, b1d);
            fma2(acc1[2][0], aB.x, b0d); fma2(acc1[2][1], aB.x, b1d);
            fma2(acc1[3][0], aB.y, b0d); fma2(acc1[3][1], aB.y, b1d);
        }
    }
    __syncthreads();   // overlay becomes sHT

    // ---- write h(+bias) transposed; fill chv rows 64..95 ----
    float* sHT = sm + O_OVER;   // [96][SA_LD]
    {
        float ba0 = sm[O_BAGG + lane], ba1 = sm[O_BAGG + lane + 32];
        #pragma unroll
        for (int p = 0; p < 4; ++p) {
            int row = warp * 8 + 2 * p;
            float2 v0 = upk2(acc1[p][0]);
            float2 v1 = upk2(acc1[p][1]);
            sHT[lane * SA_LD + row]            = v0.x + ba0;
            sHT[lane * SA_LD + row + 1]        = v0.y + ba0;
            sHT[(lane + 32) * SA_LD + row]     = v1.x + ba1;
            sHT[(lane + 32) * SA_LD + row + 1] = v1.y + ba1;
        }
    }
    for (int e = tid; e < (BM / 2) * 32; e += 256) {
        int i = e >> 5, j = e & 31;
        int v = vertices[vbase + i];
        float val = (j < 16) ? channel_dense[(size_t)v * 16 + j]
                             : channel_id_emb[(size_t)channel_ids[v] * 16 + (j - 16)];
        sHT[(64 + j) * SA_LD + 2 * i]     = val;
        sHT[(64 + j) * SA_LD + 2 * i + 1] = val;
    }
    __syncthreads();

    // ---- phase 2: hid = relu(z @ W_attn + b); score = hid . W_attn2 ----
    unsigned long long acc2[4][3];
    #pragma unroll
    for (int p = 0; p < 4; ++p) { acc2[p][0] = 0ull; acc2[p][1] = 0ull; acc2[p][2] = 0ull; }
    {
        const float* wt = sm + O_WATT;
        bool has3 = (lane < HID - 64);
        #pragma unroll 4
        for (int k = 0; k < 96; ++k) {
            ulonglong2 aA = *reinterpret_cast<const ulonglong2*>(&sHT[k * SA_LD + warp * 8]);
            ulonglong2 aB = *reinterpret_cast<const ulonglong2*>(&sHT[k * SA_LD + warp * 8 + 4]);
            float w0 = wt[k * HID + lane];
            float w1 = wt[k * HID + lane + 32];
            float w2v = has3 ? wt[k * HID + lane + 64] : 0.f;
            unsigned long long w0d = pk2(w0, w0);
            unsigned long long w1d = pk2(w1, w1);
            unsigned long long w2d = pk2(w2v, w2v);
            fma2(acc2[0][0], aA.x, w0d); fma2(acc2[0][1], aA.x, w1d); fma2(acc2[0][2], aA.x, w2d);
            fma2(acc2[1][0], aA.y, w0d); fma2(acc2[1][1], aA.y, w1d); fma2(acc2[1][2], aA.y, w2d);
            fma2(acc2[2][0], aB.x, w0d); fma2(acc2[2][1], aB.x, w1d); fma2(acc2[2][2], aB.x, w2d);
            fma2(acc2[3][0], aB.y, w0d); fma2(acc2[3][1], aB.y, w1d); fma2(acc2[3][2], aB.y, w2d);
        }
    }
    {
        float bt0 = sm[O_BATT + lane], bt1 = sm[O_BATT + lane + 32];
        float bt2 = (lane < HID - 64) ? sm[O_BATT + lane + 64] : 0.f;
        float wv0 = sm[O_W2 + lane],  wv1 = sm[O_W2 + lane + 32];
        float wv2 = (lane < HID - 64) ? sm[O_W2 + lane + 64] : 0.f;
        float p8[8];
        #pragma unroll
        for (int p = 0; p < 4; ++p) {
            float2 c0 = upk2(acc2[p][0]);
            float2 c1 = upk2(acc2[p][1]);
            float2 c2 = upk2(acc2[p][2]);
            p8[2 * p]     = fmaxf(c0.x + bt0, 0.f) * wv0 + fmaxf(c1.x + bt1, 0.f) * wv1
                          + fmaxf(c2.x + bt2, 0.f) * wv2;
            p8[2 * p + 1] = fmaxf(c0.y + bt0, 0.f) * wv0 + fmaxf(c1.y + bt1, 0.f) * wv1
                          + fmaxf(c2.y + bt2, 0.f) * wv2;
        }
        #pragma unroll
        for (int o = 16; o; o >>= 1) {
            #pragma unroll
            for (int r = 0; r < 8; ++r) p8[r] += __shfl_xor_sync(FULLMASK, p8[r], o);
        }
        if (lane == 0) {
            #pragma unroll
            for (int r = 0; r < 8; ++r) sm[O_SCORE + warp * 8 + r] = p8[r];
        }
    }
    __syncthreads();

    // ---- phase 3: per vertex finalize; warp owns vertices warp*4..+4 ----
    #pragma unroll
    for (int s = 0; s < 4; ++s) {
        int vl = warp * 4 + s;
        int vg = vbase + vl;
        float s0 = sm[O_SCORE + 2 * vl];
        float s1 = sm[O_SCORE + 2 * vl + 1];
        float mx = fmaxf(s0, s1);
        float e0 = __expf(s0 - mx), e1 = __expf(s1 - mx);
        float a0 = e0 / (e0 + e1), a1 = 1.f - a0;

        int r0i = 2 * vl, r1i = 2 * vl + 1;
        float g0 = a0 * sHT[lane * SA_LD + r0i]        + a1 * sHT[lane * SA_LD + r1i];
        float g1 = a0 * sHT[(lane + 32) * SA_LD + r0i] + a1 * sHT[(lane + 32) * SA_LD + r1i];
        out[(size_t)vg * 128 + lane]      = fmaxf(g0, 0.f);
        out[(size_t)vg * 128 + lane + 32] = fmaxf(g1, 0.f);

        float r0 = sm[O_BSELF + lane], r1 = sm[O_BSELF + lane + 32];
        const float* ws = sm + O_WSELF;
        #pragma unroll
        for (int d = 0; d < 32; ++d) {
            float xv = sHT[(64 + d) * SA_LD + r0i];
            r0 += xv * ws[d * 64 + lane];
            r1 += xv * ws[d * 64 + lane + 32];
        }
        out[(size_t)vg * 128 + 64 + lane] = fmaxf(r0, 0.f);
        out[(size_t)vg * 128 + 96 + lane] = fmaxf(r1, 0.f);
    }
}

// ---------------------------------------------------------------------------
extern "C" void kernel_launch(void* const* d_in, const int* in_sizes, int n_in,
                              void* d_out, int out_size)
{
    const float* channel_dense  = (const float*)d_in[0];
    const float* device_dense   = (const float*)d_in[1];
    const float* channel_id_emb = (const float*)d_in[2];
    const float* t0 = (const float*)d_in[3];
    const float* t1 = (const float*)d_in[4];
    const float* t2 = (const float*)d_in[5];
    const float* t3 = (const float*)d_in[6];
    const float* t4 = (const float*)d_in[7];
    const float* t5 = (const float*)d_in[8];
    const float* t6 = (const float*)d_in[9];
    const float* W_agg   = (const float*)d_in[10];
    const float* b_agg   = (const float*)d_in[11];
    const float* W_self  = (const float*)d_in[12];
    const float* b_self  = (const float*)d_in[13];
    const float* W_attn  = (const float*)d_in[14];
    const float* b_attn  = (const float*)d_in[15];
    const float* W_attn2 = (const float*)d_in[16];
    const float* b_attn2 = (const float*)d_in[17];
    const int* channel_ids   = (const int*)d_in[18];
    const int* device_cat    = (const int*)d_in[19];
    const int* vertices      = (const int*)d_in[20];
    const int* bot_neibrs    = (const int*)d_in[21];
    const int* normal_neibrs = (const int*)d_in[22];
    const int* bot_counts    = (const int*)d_in[23];
    const int* normal_counts = (const int*)d_in[24];
    float* out = (float*)d_out;

    static bool attr_set = false;
    if (!attr_set) {
        cudaFuncSetAttribute(k_fused, cudaFuncAttributeMaxDynamicSharedMemorySize, FUSED_SMEM);
        cudaFuncSetAttribute(k_fused, cudaFuncAttributePreferredSharedMemoryCarveout, 100);
        attr_set = true;
    }

    k_mean<<<MEAN_CTAS, 256>>>(device_dense, device_cat,
                               t0, t1, t2, t3, t4, t5, t6,
                               bot_neibrs, normal_neibrs,
                               bot_counts, normal_counts);

    k_fused<<<TASKS / BM, 256, FUSED_SMEM>>>(
        W_agg, b_agg, W_attn, b_attn, W_attn2, b_attn2, W_self, b_self,
        channel_dense, channel_id_emb, channel_ids, vertices, out);
}

// round 12
// speedup vs baseline: 1.2063x; 1.0212x over previous
#include <cuda_runtime.h>

#define FULLMASK 0xffffffffu

static constexpr int B_V   = 8192;
static constexpr int KN    = 64;
static constexpr int TASKS = 2 * B_V;   // 16384 (vertex, side) tasks
static constexpr int IN2   = 132;
static constexpr int HID   = 84;

// Scratch (no cudaMalloc allowed)
__device__ float g_mean[TASKS * IN2];   // 8.6 MB

// ---------------------------------------------------------------------------
// Kernel 1: masked mean (R8-proven). 8 warps/CTA, 2 warps per task.
// Tables via LDG (L1-hot). Lane c<5: dense dims; lanes 5..31: emb dims.
// t1 (4 rows) via ballot-histogram. Tail dims [128,132) strided post-pass.
// ---------------------------------------------------------------------------
static constexpr int MEAN_TPC  = 4;                    // tasks per CTA
static constexpr int MEAN_CTAS = TASKS / MEAN_TPC;     // 4096

__global__ void __launch_bounds__(256) k_mean(
    const float* __restrict__ device_dense,
    const int*   __restrict__ device_cat,
    const float* __restrict__ t0, const float* __restrict__ t1,
    const float* __restrict__ t2, const float* __restrict__ t3,
    const float* __restrict__ t4, const float* __restrict__ t5,
    const float* __restrict__ t6,
    const int* __restrict__ bot_neibrs, const int* __restrict__ normal_neibrs,
    const int* __restrict__ bot_counts, const int* __restrict__ normal_counts)
{
    __shared__ int    sCat[8][32 * 8];        // per-warp cat ids, 8 KB
    __shared__ float4 sPart[MEAN_TPC][33];    // odd-warp partials
    __shared__ float4 sTail[MEAN_TPC];

    int tid  = threadIdx.x;
    int w    = tid >> 5;          // 0..7
    int lane = tid & 31;
    int tl   = w >> 1;            // local task 0..3
    int half = w & 1;             // which 32-neighbor half

    int task = blockIdx.x * MEAN_TPC + tl;
    int b    = task >> 1;
    int side = task & 1;

    const int* neib = side ? normal_neibrs : bot_neibrs;
    int cnt = side ? normal_counts[b] : bot_counts[b];
    cnt = min(max(cnt, 1), KN);

    int myN = min(cnt - half * 32, 32);
    if (myN < 0) myN = 0;

    // own neighbor ids, one per lane
    int i0 = neib[b * KN + half * 32 + lane];

    // ---- prefetch cat ids (shfl unconditional, clamped; store predicated) ----
    int tot = myN * 7;
    for (int r = 0; r * 32 < tot; ++r) {
        int flat = r * 32 + lane;
        int n  = flat / 7;
        int tt = flat - n * 7;
        int nclamp = min(n, 31);
        int idx = __shfl_sync(FULLMASK, i0, nclamp);
        if (flat < tot)
            sCat[w][n * 8 + tt] = __ldg(device_cat + (size_t)idx * 7 + tt);
    }
    __syncwarp();

    // ---- per-lane chunk mapping ----
    // lanes 0-4: dense; 5-8:t0, 9-12:t1(ballot path), 13-16:t2,
    // 17-20:t3, 21-24:t4, 25-28:t5, 29-31:t6[0..11]
    int  c       = lane;
    int  m       = (c < 5) ? 0 : (c - 5);
    int  t       = m >> 2;
    int  e4      = (m & 3) * 4;
    bool isT1    = (t == 1) && (c >= 5);
    bool isDense = (c < 5) || isT1;        // t1 lanes ride the dense dup address
    const float* base;
    switch (t) {
        case 0: base = t0; break; case 1: base = t1; break;
        case 2: base = t2; break; case 3: base = t3; break;
        case 4: base = t4; break; case 5: base = t5; break;
        default: base = t6; break;
    }
    int denseSub = (c < 5) ? 4 * c : 0;    // t1 lanes dup lane 0's chunk

    // ---- main accumulation over own range ----
    float4 acc = make_float4(0.f, 0.f, 0.f, 0.f);
    #pragma unroll 8
    for (int n = 0; n < myN; ++n) {
        int idx = __shfl_sync(FULLMASK, i0, n);
        int cat = sCat[w][n * 8 + t];             // broadcast LDS
        const float4* p = isDense
            ? reinterpret_cast<const float4*>(device_dense + (size_t)idx * 20 + denseSub)
            : reinterpret_cast<const float4*>(base + (size_t)cat * 16 + e4);
        float4 v = __ldg(p);
        acc.x += v.x; acc.y += v.y; acc.z += v.z; acc.w += v.w;
    }

    // ---- t1 contribution via ballot histogram (4 possible rows) ----
    {
        int c1 = sCat[w][lane * 8 + 1];           // lane n -> neighbor n's cat1
        float4 accT1 = make_float4(0.f, 0.f, 0.f, 0.f);
        #pragma unroll
        for (int v = 0; v < 4; ++v) {
            unsigned mk = __ballot_sync(FULLMASK, (lane < myN) && (c1 == v));
            float cv = (float)__popc(mk);
            if (isT1) {
                float4 row = __ldg(reinterpret_cast<const float4*>(t1 + v * 16 + e4));
                accT1.x += cv * row.x; accT1.y += cv * row.y;
                accT1.z += cv * row.z; accT1.w += cv * row.w;
            }
        }
        if (isT1) acc = accT1;
    }

    // ---- tail chunk (dims 128..131 = t6 row floats 12..15), strided ----
    float4 acc2 = make_float4(0.f, 0.f, 0.f, 0.f);
    for (int n = lane; n < myN; n += 32) {
        int c6 = sCat[w][n * 8 + 6];
        float4 v = __ldg(reinterpret_cast<const float4*>(t6 + (size_t)c6 * 16 + 12));
        acc2.x += v.x; acc2.y += v.y; acc2.z += v.z; acc2.w += v.w;
    }
    #pragma unroll
    for (int o = 16; o; o >>= 1) {
        acc2.x += __shfl_xor_sync(FULLMASK, acc2.x, o);
        acc2.y += __shfl_xor_sync(FULLMASK, acc2.y, o);
        acc2.z += __shfl_xor_sync(FULLMASK, acc2.z, o);
        acc2.w += __shfl_xor_sync(FULLMASK, acc2.w, o);
    }

    // ---- combine partner halves ----
    if (half == 1) {
        sPart[tl][lane] = acc;
        if (lane == 0) sTail[tl] = acc2;
    }
    __syncthreads();
    if (half == 0) {
        float4 p = sPart[tl][lane];
        acc.x += p.x; acc.y += p.y; acc.z += p.z; acc.w += p.w;
        float inv = 1.0f / (float)cnt;
        float4 o4 = make_float4(acc.x * inv, acc.y * inv, acc.z * inv, acc.w * inv);
        int outOff = (c < 5) ? 4 * c : 20 + 4 * m;
        *reinterpret_cast<float4*>(g_mean + (size_t)task * IN2 + outOff) = o4;
        if (lane == 0) {
            float4 pt = sTail[tl];
            float4 o2 = make_float4((acc2.x + pt.x) * inv, (acc2.y + pt.y) * inv,
                                    (acc2.z + pt.z) * inv, (acc2.w + pt.w) * inv);
            *reinterpret_cast<float4*>(g_mean + (size_t)task * IN2 + 128) = o2;
        }
    }
}

// ---------------------------------------------------------------------------
// packed f32x2 helpers (sm_100+)
// ---------------------------------------------------------------------------
__device__ __forceinline__ unsigned long long pk2(float lo, float hi) {
    unsigned long long r;
    asm("mov.b64 %0, {%1, %2};" : "=l"(r) : "f"(lo), "f"(hi));
    return r;
}
__device__ __forceinline__ void fma2(unsigned long long& d,
                                     unsigned long long a, unsigned long long b) {
    asm("fma.rn.f32x2 %0, %1, %2, %0;" : "+l"(d) : "l"(a), "l"(b));
}
__device__ __forceinline__ float2 upk2(unsigned long long v) {
    float2 f;
    asm("mov.b64 {%0, %1}, %2;" : "=f"(f.x), "=f"(f.y) : "l"(v));
    return f;
}

// ---------------------------------------------------------------------------
// Kernel 2: fused MLP chain. BM=128 tasks/CTA, 512 threads (16 warps),
// grid = 128 CTAs -> EXACTLY ONE WAVE on 148 SMs, 4 warps/SMSP.
// Per-warp work identical to the proven 8-rows-per-warp structure.
// ---------------------------------------------------------------------------
static constexpr int BM = 128;
static constexpr int FTHREADS = 512;

static constexpr int O_WAGG  = 0;                       // [132][64]
static constexpr int O_WATT  = O_WAGG  + 132 * 64;      // [96][84]
static constexpr int O_WSELF = O_WATT  + 96 * 84;       // [32][64]
static constexpr int O_W2    = O_WSELF + 32 * 64;       // [84] pad 96
static constexpr int O_BAGG  = O_W2    + 96;
static constexpr int O_BATT  = O_BAGG  + 64;            // [84] pad 96
static constexpr int O_BSELF = O_BATT  + 96;
static constexpr int O_B2    = O_BSELF + 64;            // pad 16
static constexpr int O_SCORE = O_B2    + 16;            // [128]
static constexpr int O_OVER  = O_SCORE + 128;           // overlay sA[132][132]/sHT[96][132]
static constexpr int SA_LD   = 132;
static constexpr int SMEM_FLOATS = O_OVER + 132 * SA_LD;
static constexpr int FUSED_SMEM  = SMEM_FLOATS * 4;     // ~146 KB

__global__ void __launch_bounds__(FTHREADS, 1) k_fused(
    const float* __restrict__ W_agg,  const float* __restrict__ b_agg,
    const float* __restrict__ W_attn, const float* __restrict__ b_attn,
    const float* __restrict__ W_attn2,const float* __restrict__ b_attn2,
    const float* __restrict__ W_self, const float* __restrict__ b_self,
    const float* __restrict__ channel_dense,
    const float* __restrict__ channel_id_emb,
    const int*   __restrict__ channel_ids,
    const int*   __restrict__ vertices,
    float* __restrict__ out)
{
    extern __shared__ float sm[];
    int tid  = threadIdx.x;
    int warp = tid >> 5;            // 0..15
    int lane = tid & 31;
    int tbase = blockIdx.x * BM;
    int vbase = blockIdx.x * (BM / 2);

    // ---- weights ----
    for (int e = tid; e < (132 * 64) / 4; e += FTHREADS)
        reinterpret_cast<float4*>(sm + O_WAGG)[e] = reinterpret_cast<const float4*>(W_agg)[e];
    for (int e = tid; e < (96 * 84) / 4; e += FTHREADS)
        reinterpret_cast<float4*>(sm + O_WATT)[e] = reinterpret_cast<const float4*>(W_attn)[e];
    for (int e = tid; e < (32 * 64) / 4; e += FTHREADS)
        reinterpret_cast<float4*>(sm + O_WSELF)[e] = reinterpret_cast<const float4*>(W_self)[e];
    if (tid < 84) sm[O_W2 + tid]   = W_attn2[tid];
    if (tid < 64) sm[O_BAGG + tid] = b_agg[tid];
    if (tid >= 64 && tid < 148)  sm[O_BATT + tid - 64]   = b_attn[tid - 64];
    if (tid >= 148 && tid < 212) sm[O_BSELF + tid - 148] = b_self[tid - 148];
    if (tid == 212) sm[O_B2] = b_attn2[0];

    // ---- stage A (transposed): sA[k][row], 128 rows ----
    float* sA = sm + O_OVER;
    for (int e = tid; e < BM * 33; e += FTHREADS) {
        int row = e / 33, cch = e - row * 33;
        float4 v = *reinterpret_cast<const float4*>(g_mean + (size_t)(tbase + row) * IN2 + cch * 4);
        sA[(4 * cch + 0) * SA_LD + row] = v.x;
        sA[(4 * cch + 1) * SA_LD + row] = v.y;
        sA[(4 * cch + 2) * SA_LD + row] = v.z;
        sA[(4 * cch + 3) * SA_LD + row] = v.w;
    }
    __syncthreads();

    // ---- phase 1: h = sA^T @ W_agg ; warp -> 8 rows (4 pairs), lane -> 2 cols
    unsigned long long acc1[4][2];
    #pragma unroll
    for (int p = 0; p < 4; ++p) { acc1[p][0] = 0ull; acc1[p][1] = 0ull; }
    {
        const float* wa = sm + O_WAGG;
        #pragma unroll 4
        for (int k = 0; k < IN2; ++k) {
            ulonglong2 aA = *reinterpret_cast<const ulonglong2*>(&sA[k * SA_LD + warp * 8]);
            ulonglong2 aB = *reinterpret_cast<const ulonglong2*>(&sA[k * SA_LD + warp * 8 + 4]);
            unsigned long long b0d = pk2(wa[k * 64 + lane],      wa[k * 64 + lane]);
            unsigned long long b1d = pk2(wa[k * 64 + lane + 32], wa[k * 64 + lane + 32]);
            fma2(acc1[0][0], aA.x, b0d); fma2(acc1[0][1], aA.x, b1d);
            fma2(acc1[1][0], aA.y, b0d); fma2(acc1[1][1], aA.y, b1d);
            fma2(acc1[2][0], aB.x, b0d); fma2(acc1[2][1], aB.x, b1d);
            fma2(acc1[3][0], aB.y, b0d); fma2(acc1[3][1], aB.y, b1d);
        }
    }
    __syncthreads();   // overlay becomes sHT

    // ---- write h(+bias) transposed; fill chv rows 64..95 ----
    float* sHT = sm + O_OVER;   // [96][SA_LD]
    {
        float ba0 = sm[O_BAGG + lane], ba1 = sm[O_BAGG + lane + 32];
        #pragma unroll
        for (int p = 0; p < 4; ++p) {
            int row = warp * 8 + 2 * p;
            float2 v0 = upk2(acc1[p][0]);
            float2 v1 = upk2(acc1[p][1]);
            sHT[lane * SA_LD + row]            = v0.x + ba0;
            sHT[lane * SA_LD + row + 1]        = v0.y + ba0;
            sHT[(lane + 32) * SA_LD + row]     = v1.x + ba1;
            sHT[(lane + 32) * SA_LD + row + 1] = v1.y + ba1;
        }
    }
    for (int e = tid; e < (BM / 2) * 32; e += FTHREADS) {
        int i = e >> 5, j = e & 31;
        int v = vertices[vbase + i];
        float val = (j < 16) ? channel_dense[(size_t)v * 16 + j]
                             : channel_id_emb[(size_t)channel_ids[v] * 16 + (j - 16)];
        sHT[(64 + j) * SA_LD + 2 * i]     = val;
        sHT[(64 + j) * SA_LD + 2 * i + 1] = val;
    }
    __syncthreads();

    // ---- phase 2: hid = relu(z @ W_attn + b); score = hid . W_attn2 ----
    unsigned long long acc2[4][3];
    #pragma unroll
    for (int p = 0; p < 4; ++p) { acc2[p][0] = 0ull; acc2[p][1] = 0ull; acc2[p][2] = 0ull; }
    {
        const float* wt = sm + O_WATT;
        bool has3 = (lane < HID - 64);
        #pragma unroll 4
        for (int k = 0; k < 96; ++k) {
            ulonglong2 aA = *reinterpret_cast<const ulonglong2*>(&sHT[k * SA_LD + warp * 8]);
            ulonglong2 aB = *reinterpret_cast<const ulonglong2*>(&sHT[k * SA_LD + warp * 8 + 4]);
            float w0 = wt[k * HID + lane];
            float w1 = wt[k * HID + lane + 32];
            float w2v = has3 ? wt[k * HID + lane + 64] : 0.f;
            unsigned long long w0d = pk2(w0, w0);
            unsigned long long w1d = pk2(w1, w1);
            unsigned long long w2d = pk2(w2v, w2v);
            fma2(acc2[0][0], aA.x, w0d); fma2(acc2[0][1], aA.x, w1d); fma2(acc2[0][2], aA.x, w2d);
            fma2(acc2[1][0], aA.y, w0d); fma2(acc2[1][1], aA.y, w1d); fma2(acc2[1][2], aA.y, w2d);
            fma2(acc2[2][0], aB.x, w0d); fma2(acc2[2][1], aB.x, w1d); fma2(acc2[2][2], aB.x, w2d);
            fma2(acc2[3][0], aB.y, w0d); fma2(acc2[3][1], aB.y, w1d); fma2(acc2[3][2], aB.y, w2d);
        }
    }
    {
        float bt0 = sm[O_BATT + lane], bt1 = sm[O_BATT + lane + 32];
        float bt2 = (lane < HID - 64) ? sm[O_BATT + lane + 64] : 0.f;
        float wv0 = sm[O_W2 + lane],  wv1 = sm[O_W2 + lane + 32];
        float wv2 = (lane < HID - 64) ? sm[O_W2 + lane + 64] : 0.f;
        float p8[8];
        #pragma unroll
        for (int p = 0; p < 4; ++p) {
            float2 c0 = upk2(acc2[p][0]);
            float2 c1 = upk2(acc2[p][1]);
            float2 c2 = upk2(acc2[p][2]);
            p8[2 * p]     = fmaxf(c0.x + bt0, 0.f) * wv0 + fmaxf(c1.x + bt1, 0.f) * wv1
                          + fmaxf(c2.x + bt2, 0.f) * wv2;
            p8[2 * p + 1] = fmaxf(c0.y + bt0, 0.f) * wv0 + fmaxf(c1.y + bt1, 0.f) * wv1
                          + fmaxf(c2.y + bt2, 0.f) * wv2;
        }
        #pragma unroll
        for (int o = 16; o; o >>= 1) {
            #pragma unroll
            for (int r = 0; r < 8; ++r) p8[r] += __shfl_xor_sync(FULLMASK, p8[r], o);
        }
        if (lane == 0) {
            #pragma unroll
            for (int r = 0; r < 8; ++r) sm[O_SCORE + warp * 8 + r] = p8[r];
        }
    }
    __syncthreads();

    // ---- phase 3: per vertex finalize; warp owns vertices warp*4..+4 ----
    #pragma unroll
    for (int s = 0; s < 4; ++s) {
        int vl = warp * 4 + s;                 // 16 warps x 4 = 64 vertices
        int vg = vbase + vl;
        float s0 = sm[O_SCORE + 2 * vl];
        float s1 = sm[O_SCORE + 2 * vl + 1];
        float mx = fmaxf(s0, s1);
        float e0 = __expf(s0 - mx), e1 = __expf(s1 - mx);
        float a0 = e0 / (e0 + e1), a1 = 1.f - a0;

        int r0i = 2 * vl, r1i = 2 * vl + 1;
        float g0 = a0 * sHT[lane * SA_LD + r0i]        + a1 * sHT[lane * SA_LD + r1i];
        float g1 = a0 * sHT[(lane + 32) * SA_LD + r0i] + a1 * sHT[(lane + 32) * SA_LD + r1i];
        out[(size_t)vg * 128 + lane]      = fmaxf(g0, 0.f);
        out[(size_t)vg * 128 + lane + 32] = fmaxf(g1, 0.f);

        float r0 = sm[O_BSELF + lane], r1 = sm[O_BSELF + lane + 32];
        const float* ws = sm + O_WSELF;
        #pragma unroll
        for (int d = 0; d < 32; ++d) {
            float xv = sHT[(64 + d) * SA_LD + r0i];
            r0 += xv * ws[d * 64 + lane];
            r1 += xv * ws[d * 64 + lane + 32];
        }
        out[(size_t)vg * 128 + 64 + lane] = fmaxf(r0, 0.f);
        out[(size_t)vg * 128 + 96 + lane] = fmaxf(r1, 0.f);
    }
}

// ---------------------------------------------------------------------------
extern "C" void kernel_launch(void* const* d_in, const int* in_sizes, int n_in,
                              void* d_out, int out_size)
{
    const float* channel_dense  = (const float*)d_in[0];
    const float* device_dense   = (const float*)d_in[1];
    const float* channel_id_emb = (const float*)d_in[2];
    const float* t0 = (const float*)d_in[3];
    const float* t1 = (const float*)d_in[4];
    const float* t2 = (const float*)d_in[5];
    const float* t3 = (const float*)d_in[6];
    const float* t4 = (const float*)d_in[7];
    const float* t5 = (const float*)d_in[8];
    const float* t6 = (const float*)d_in[9];
    const float* W_agg   = (const float*)d_in[10];
    const float* b_agg   = (const float*)d_in[11];
    const float* W_self  = (const float*)d_in[12];
    const float* b_self  = (const float*)d_in[13];
    const float* W_attn  = (const float*)d_in[14];
    const float* b_attn  = (const float*)d_in[15];
    const float* W_attn2 = (const float*)d_in[16];
    const float* b_attn2 = (const float*)d_in[17];
    const int* channel_ids   = (const int*)d_in[18];
    const int* device_cat    = (const int*)d_in[19];
    const int* vertices      = (const int*)d_in[20];
    const int* bot_neibrs    = (const int*)d_in[21];
    const int* normal_neibrs = (const int*)d_in[22];
    const int* bot_counts    = (const int*)d_in[23];
    const int* normal_counts = (const int*)d_in[24];
    float* out = (float*)d_out;

    static bool attr_set = false;
    if (!attr_set) {
        cudaFuncSetAttribute(k_fused, cudaFuncAttributeMaxDynamicSharedMemorySize, FUSED_SMEM);
        cudaFuncSetAttribute(k_fused, cudaFuncAttributePreferredSharedMemoryCarveout, 100);
        attr_set = true;
    }

    k_mean<<<MEAN_CTAS, 256>>>(device_dense, device_cat,
                               t0, t1, t2, t3, t4, t5, t6,
                               bot_neibrs, normal_neibrs,
                               bot_counts, normal_counts);

    k_fused<<<TASKS / BM, FTHREADS, FUSED_SMEM>>>(
        W_agg, b_agg, W_attn, b_attn, W_attn2, b_attn2, W_self, b_self,
        channel_dense, channel_id_emb, channel_ids, vertices, out);
}